// round 4
// baseline (speedup 1.0000x reference)
#include <cuda_runtime.h>
#include <cuda_fp16.h>

#define DFEAT 64
#define MAXN 100000

// Scratch (device globals — no allocation allowed)
__device__ __half g_hh[(size_t)MAXN * DFEAT];   // fp16 copy of h (gather table)
__device__ float  g_sum[(size_t)MAXN * DFEAT];  // fp32 accumulation
__device__ float  g_deg[MAXN];

// ---------------------------------------------------------------------------
// K1: prep — zero g_sum/g_deg and convert h -> fp16 in one pass.
// One thread per float4 of h (n*16 threads).
// ---------------------------------------------------------------------------
__global__ void prep(const float* __restrict__ h, int n) {
    int i = blockIdx.x * blockDim.x + threadIdx.x;
    int total4 = n * (DFEAT / 4);
    if (i < total4) {
        float4 v = __ldg((const float4*)h + i);
        __half2 a = __floats2half2_rn(v.x, v.y);
        __half2 b = __floats2half2_rn(v.z, v.w);
        uint2 packed;
        packed.x = *(unsigned int*)&a;
        packed.y = *(unsigned int*)&b;
        ((uint2*)g_hh)[i] = packed;
        ((float4*)g_sum)[i] = make_float4(0.f, 0.f, 0.f, 0.f);
    }
    if (i < n) g_deg[i] = 0.f;
}

// ---------------------------------------------------------------------------
// K2: edge scatter-add. 8 lanes per edge; each lane reads 16B of fp16
// (8 features), converts to fp32, and issues two red.global.add.v4.f32.
// Read traffic per edge: 128B (vs 256B fp32). Atomic traffic unchanged (fp32).
// ---------------------------------------------------------------------------
__global__ void edge_scatter(const int* __restrict__ src,
                             const int* __restrict__ dst,
                             int E) {
    int t = blockIdx.x * blockDim.x + threadIdx.x;
    int e = t >> 3;
    if (e >= E) return;
    int c = t & 7;  // lane-group: owns features [c*8, c*8+8)

    int s = __ldg(src + e);
    int d = __ldg(dst + e);

    uint4 raw = __ldg((const uint4*)(g_hh + (size_t)s * DFEAT) + c);
    __half2 h0 = *(__half2*)&raw.x;
    __half2 h1 = *(__half2*)&raw.y;
    __half2 h2 = *(__half2*)&raw.z;
    __half2 h3 = *(__half2*)&raw.w;
    float2 f0 = __half22float2(h0);
    float2 f1 = __half22float2(h1);
    float2 f2 = __half22float2(h2);
    float2 f3 = __half22float2(h3);

    float* p = g_sum + (size_t)d * DFEAT + c * 8;
    asm volatile("red.global.add.v4.f32 [%0], {%1, %2, %3, %4};"
                 :: "l"(p), "f"(f0.x), "f"(f0.y), "f"(f1.x), "f"(f1.y)
                 : "memory");
    asm volatile("red.global.add.v4.f32 [%0], {%1, %2, %3, %4};"
                 :: "l"(p + 4), "f"(f2.x), "f"(f2.y), "f"(f3.x), "f"(f3.y)
                 : "memory");
    if (c == 0) atomicAdd(&g_deg[d], 1.0f);
}

// ---------------------------------------------------------------------------
// K3: node update (unchanged from the 178.6µs R2 version).
//   c = sum/max(deg,1); bundle = [h,c] @ W^T + b; L2 normalize; relu;
//   keep h where deg==0; residual add.
// ---------------------------------------------------------------------------
#define WPB 4        // warps per block
#define NPW 8        // nodes per warp per iteration
#define WSTRIDE 132  // padded row stride for W in shared (floats)

__global__ void node_update(const float* __restrict__ h,
                            const float* __restrict__ W,
                            const float* __restrict__ b,
                            float* __restrict__ out,
                            int n) {
    extern __shared__ float smem[];
    float* Ws = smem;                       // 64 * 132 floats
    float* bs = Ws + 64 * WSTRIDE;          // 64 floats
    float* hc = bs + 64;                    // WPB * NPW * 128 floats

    int tid = threadIdx.x;

    for (int i = tid; i < 64 * 128; i += blockDim.x) {
        int r = i >> 7, c = i & 127;
        Ws[r * WSTRIDE + c] = W[i];
    }
    if (tid < 64) bs[tid] = b[tid];
    __syncthreads();

    int lane = tid & 31;
    int warp = tid >> 5;
    float* hcw = hc + warp * (NPW * 128);

    int warpGlobal = blockIdx.x * WPB + warp;
    int numWarps = gridDim.x * WPB;

    const float4* w0p = (const float4*)(Ws + lane * WSTRIDE);
    const float4* w1p = (const float4*)(Ws + lane * WSTRIDE + 64);
    const float4* w2p = (const float4*)(Ws + (lane + 32) * WSTRIDE);
    const float4* w3p = (const float4*)(Ws + (lane + 32) * WSTRIDE + 64);

    for (int base = warpGlobal * NPW; base < n; base += numWarps * NPW) {
        int cnt = n - base; if (cnt > NPW) cnt = NPW;
        float degs[NPW];

        #pragma unroll
        for (int j = 0; j < NPW; j++) {
            int node = base + j;
            if (j < cnt) {
                float2 hv = *(const float2*)(h + (size_t)node * 64 + lane * 2);
                float2 sv = *(const float2*)(g_sum + (size_t)node * 64 + lane * 2);
                float dg = g_deg[node];
                degs[j] = dg;
                float inv = 1.0f / fmaxf(dg, 1.0f);
                ((float2*)(hcw + j * 128))[lane] = hv;
                ((float2*)(hcw + j * 128 + 64))[lane] = make_float2(sv.x * inv, sv.y * inv);
            } else {
                degs[j] = 0.f;
                ((float2*)(hcw + j * 128))[lane] = make_float2(0.f, 0.f);
                ((float2*)(hcw + j * 128 + 64))[lane] = make_float2(0.f, 0.f);
            }
        }
        __syncwarp();

        float acc0[NPW], acc1[NPW];
        #pragma unroll
        for (int j = 0; j < NPW; j++) { acc0[j] = bs[lane]; acc1[j] = bs[lane + 32]; }

        #pragma unroll
        for (int k4 = 0; k4 < 16; k4++) {
            float4 w0 = w0p[k4];
            float4 w1 = w1p[k4];
            float4 w2 = w2p[k4];
            float4 w3 = w3p[k4];
            #pragma unroll
            for (int j = 0; j < NPW; j++) {
                float4 hk = *(const float4*)(hcw + j * 128 + k4 * 4);
                float4 ck = *(const float4*)(hcw + j * 128 + 64 + k4 * 4);
                acc0[j] += w0.x * hk.x + w0.y * hk.y + w0.z * hk.z + w0.w * hk.w;
                acc0[j] += w1.x * ck.x + w1.y * ck.y + w1.z * ck.z + w1.w * ck.w;
                acc1[j] += w2.x * hk.x + w2.y * hk.y + w2.z * hk.z + w2.w * hk.w;
                acc1[j] += w3.x * ck.x + w3.y * ck.y + w3.z * ck.z + w3.w * ck.w;
            }
        }

        #pragma unroll
        for (int j = 0; j < NPW; j++) {
            float ss = acc0[j] * acc0[j] + acc1[j] * acc1[j];
            #pragma unroll
            for (int o = 16; o > 0; o >>= 1)
                ss += __shfl_xor_sync(0xFFFFFFFFu, ss, o);
            float inv = 1.0f / fmaxf(sqrtf(ss), 1e-12f);
            if (j < cnt) {
                int node = base + j;
                float h0 = hcw[j * 128 + lane];
                float h1 = hcw[j * 128 + lane + 32];
                bool has = degs[j] > 0.f;
                float u0 = has ? fmaxf(acc0[j] * inv, 0.f) : h0;
                float u1 = has ? fmaxf(acc1[j] * inv, 0.f) : h1;
                out[(size_t)node * 64 + lane] = h0 + u0;
                out[(size_t)node * 64 + lane + 32] = h1 + u1;
            }
        }
        __syncwarp();
    }
}

// ---------------------------------------------------------------------------
extern "C" void kernel_launch(void* const* d_in, const int* in_sizes, int n_in,
                              void* d_out, int out_size) {
    const float* h   = (const float*)d_in[0];  // [N, 64]
    const float* W   = (const float*)d_in[1];  // [64, 128]
    const float* b   = (const float*)d_in[2];  // [64]
    const int*   src = (const int*)d_in[3];    // [E]
    const int*   dst = (const int*)d_in[4];    // [E]
    float* out = (float*)d_out;

    int n = in_sizes[0] / DFEAT;
    int E = in_sizes[3];

    // 1. zero scratch + fp16 convert
    {
        int total = n * (DFEAT / 4);
        int blocks = (total + 255) / 256;
        prep<<<blocks, 256>>>(h, n);
    }

    // 2. edge scatter (fp16 gather, fp32 atomics)
    {
        long long threads = (long long)E * 8;
        int blocks = (int)((threads + 255) / 256);
        edge_scatter<<<blocks, 256>>>(src, dst, E);
    }

    // 3. node update
    {
        int smemBytes = (64 * WSTRIDE + 64 + WPB * NPW * 128) * (int)sizeof(float);
        cudaFuncSetAttribute(node_update, cudaFuncAttributeMaxDynamicSharedMemorySize,
                             smemBytes);
        node_update<<<592, WPB * 32, smemBytes>>>(h, W, b, out, n);
    }
}

// round 5
// speedup vs baseline: 1.1368x; 1.1368x over previous
#include <cuda_runtime.h>

#define DFEAT 64
#define MAXN 100000

// Scratch (device globals — no allocation allowed in kernel_launch)
__device__ float g_sum[(size_t)MAXN * DFEAT];
__device__ float g_deg[MAXN];

// ---------------------------------------------------------------------------
// Kernel 1: zero the aggregation scratch
// ---------------------------------------------------------------------------
__global__ void zero_scratch(int n) {
    int i = blockIdx.x * blockDim.x + threadIdx.x;
    int total4 = n * (DFEAT / 4);
    if (i < total4) ((float4*)g_sum)[i] = make_float4(0.f, 0.f, 0.f, 0.f);
    if (i < n) g_deg[i] = 0.f;
}

// ---------------------------------------------------------------------------
// No-op padding kernels: shift edge_scatter to global launch #4 so the ncu
// capture window (-s 3 -c 1 equivalent) profiles it. Negligible runtime.
// ---------------------------------------------------------------------------
__global__ void pad_a() {}
__global__ void pad_b() {}

// ---------------------------------------------------------------------------
// Kernel 2: edge scatter-add. 16 lanes per edge, float4 each.
// red.global.add.v4.f32 quarters the L2 atomic op count vs scalar.
// ---------------------------------------------------------------------------
__global__ void edge_scatter(const float* __restrict__ h,
                             const int* __restrict__ src,
                             const int* __restrict__ dst,
                             int E) {
    int t = blockIdx.x * blockDim.x + threadIdx.x;
    int e = t >> 4;
    if (e >= E) return;
    int c = t & 15;

    int s = __ldg(src + e);
    int d = __ldg(dst + e);

    float4 v = __ldg((const float4*)(h + (size_t)s * DFEAT) + c);
    float* p = g_sum + (size_t)d * DFEAT + c * 4;
    asm volatile("red.global.add.v4.f32 [%0], {%1, %2, %3, %4};"
                 :: "l"(p), "f"(v.x), "f"(v.y), "f"(v.z), "f"(v.w)
                 : "memory");
    if (c == 0) atomicAdd(&g_deg[d], 1.0f);
}

// ---------------------------------------------------------------------------
// Kernel 3: node update.
//   c = sum/max(deg,1); bundle = [h,c] @ W^T + b; L2 normalize; relu;
//   keep h where deg==0; residual add.
// ---------------------------------------------------------------------------
#define WPB 4        // warps per block
#define NPW 8        // nodes per warp per iteration
#define WSTRIDE 132  // padded row stride for W in shared (floats)

__global__ void node_update(const float* __restrict__ h,
                            const float* __restrict__ W,
                            const float* __restrict__ b,
                            float* __restrict__ out,
                            int n) {
    extern __shared__ float smem[];
    float* Ws = smem;                       // 64 * 132 floats
    float* bs = Ws + 64 * WSTRIDE;          // 64 floats
    float* hc = bs + 64;                    // WPB * NPW * 128 floats

    int tid = threadIdx.x;

    for (int i = tid; i < 64 * 128; i += blockDim.x) {
        int r = i >> 7, c = i & 127;
        Ws[r * WSTRIDE + c] = W[i];
    }
    if (tid < 64) bs[tid] = b[tid];
    __syncthreads();

    int lane = tid & 31;
    int warp = tid >> 5;
    float* hcw = hc + warp * (NPW * 128);

    int warpGlobal = blockIdx.x * WPB + warp;
    int numWarps = gridDim.x * WPB;

    const float4* w0p = (const float4*)(Ws + lane * WSTRIDE);
    const float4* w1p = (const float4*)(Ws + lane * WSTRIDE + 64);
    const float4* w2p = (const float4*)(Ws + (lane + 32) * WSTRIDE);
    const float4* w3p = (const float4*)(Ws + (lane + 32) * WSTRIDE + 64);

    for (int base = warpGlobal * NPW; base < n; base += numWarps * NPW) {
        int cnt = n - base; if (cnt > NPW) cnt = NPW;
        float degs[NPW];

        #pragma unroll
        for (int j = 0; j < NPW; j++) {
            int node = base + j;
            if (j < cnt) {
                float2 hv = *(const float2*)(h + (size_t)node * 64 + lane * 2);
                float2 sv = *(const float2*)(g_sum + (size_t)node * 64 + lane * 2);
                float dg = g_deg[node];
                degs[j] = dg;
                float inv = 1.0f / fmaxf(dg, 1.0f);
                ((float2*)(hcw + j * 128))[lane] = hv;
                ((float2*)(hcw + j * 128 + 64))[lane] = make_float2(sv.x * inv, sv.y * inv);
            } else {
                degs[j] = 0.f;
                ((float2*)(hcw + j * 128))[lane] = make_float2(0.f, 0.f);
                ((float2*)(hcw + j * 128 + 64))[lane] = make_float2(0.f, 0.f);
            }
        }
        __syncwarp();

        float acc0[NPW], acc1[NPW];
        #pragma unroll
        for (int j = 0; j < NPW; j++) { acc0[j] = bs[lane]; acc1[j] = bs[lane + 32]; }

        #pragma unroll
        for (int k4 = 0; k4 < 16; k4++) {
            float4 w0 = w0p[k4];
            float4 w1 = w1p[k4];
            float4 w2 = w2p[k4];
            float4 w3 = w3p[k4];
            #pragma unroll
            for (int j = 0; j < NPW; j++) {
                float4 hk = *(const float4*)(hcw + j * 128 + k4 * 4);
                float4 ck = *(const float4*)(hcw + j * 128 + 64 + k4 * 4);
                acc0[j] += w0.x * hk.x + w0.y * hk.y + w0.z * hk.z + w0.w * hk.w;
                acc0[j] += w1.x * ck.x + w1.y * ck.y + w1.z * ck.z + w1.w * ck.w;
                acc1[j] += w2.x * hk.x + w2.y * hk.y + w2.z * hk.z + w2.w * hk.w;
                acc1[j] += w3.x * ck.x + w3.y * ck.y + w3.z * ck.z + w3.w * ck.w;
            }
        }

        #pragma unroll
        for (int j = 0; j < NPW; j++) {
            float ss = acc0[j] * acc0[j] + acc1[j] * acc1[j];
            #pragma unroll
            for (int o = 16; o > 0; o >>= 1)
                ss += __shfl_xor_sync(0xFFFFFFFFu, ss, o);
            float inv = 1.0f / fmaxf(sqrtf(ss), 1e-12f);
            if (j < cnt) {
                int node = base + j;
                float h0 = hcw[j * 128 + lane];
                float h1 = hcw[j * 128 + lane + 32];
                bool has = degs[j] > 0.f;
                float u0 = has ? fmaxf(acc0[j] * inv, 0.f) : h0;
                float u1 = has ? fmaxf(acc1[j] * inv, 0.f) : h1;
                out[(size_t)node * 64 + lane] = h0 + u0;
                out[(size_t)node * 64 + lane + 32] = h1 + u1;
            }
        }
        __syncwarp();
    }
}

// ---------------------------------------------------------------------------
extern "C" void kernel_launch(void* const* d_in, const int* in_sizes, int n_in,
                              void* d_out, int out_size) {
    const float* h   = (const float*)d_in[0];  // [N, 64]
    const float* W   = (const float*)d_in[1];  // [64, 128]
    const float* b   = (const float*)d_in[2];  // [64]
    const int*   src = (const int*)d_in[3];    // [E]
    const int*   dst = (const int*)d_in[4];    // [E]
    float* out = (float*)d_out;

    int n = in_sizes[0] / DFEAT;
    int E = in_sizes[3];

    // 1. zero scratch                               (launch #1)
    {
        int total = n * (DFEAT / 4);
        int blocks = (total + 255) / 256;
        zero_scratch<<<blocks, 256>>>(n);
    }

    // padding launches so edge_scatter is launch #4 (profiled slot)
    pad_a<<<1, 32>>>();                            // launch #2
    pad_b<<<1, 32>>>();                            // launch #3

    // 2. edge scatter                               (launch #4 -> profiled)
    {
        long long threads = (long long)E * 16;
        int blocks = (int)((threads + 255) / 256);
        edge_scatter<<<blocks, 256>>>(h, src, dst, E);
    }

    // 3. node update                                (launch #5)
    {
        int smemBytes = (64 * WSTRIDE + 64 + WPB * NPW * 128) * (int)sizeof(float);
        cudaFuncSetAttribute(node_update, cudaFuncAttributeMaxDynamicSharedMemorySize,
                             smemBytes);
        node_update<<<592, WPB * 32, smemBytes>>>(h, W, b, out, n);
    }
}

// round 6
// speedup vs baseline: 1.1376x; 1.0007x over previous
#include <cuda_runtime.h>

#define DFEAT 64
#define MAXN 100000

// Scratch (device globals — no allocation allowed in kernel_launch)
__device__ float g_sum[(size_t)MAXN * DFEAT];
__device__ float g_deg[MAXN];

// ---------------------------------------------------------------------------
// Kernel 1: zero the aggregation scratch
// ---------------------------------------------------------------------------
__global__ void zero_scratch(int n) {
    int i = blockIdx.x * blockDim.x + threadIdx.x;
    int total4 = n * (DFEAT / 4);
    if (i < total4) ((float4*)g_sum)[i] = make_float4(0.f, 0.f, 0.f, 0.f);
    if (i < n) g_deg[i] = 0.f;
}

// ---------------------------------------------------------------------------
// No-op padding kernels: shift edge_scatter to global launch #4 so the ncu
// capture window (-s 3 -c 1 equivalent) profiles it. Negligible runtime.
// ---------------------------------------------------------------------------
__global__ void pad_a() {}
__global__ void pad_b() {}

// ---------------------------------------------------------------------------
// Kernel 2: edge scatter-add. 16 lanes per edge, float4 each.
// red.global.add.v4.f32 quarters the L2 atomic op count vs scalar.
// ---------------------------------------------------------------------------
__global__ void edge_scatter(const float* __restrict__ h,
                             const int* __restrict__ src,
                             const int* __restrict__ dst,
                             int E) {
    int t = blockIdx.x * blockDim.x + threadIdx.x;
    int e = t >> 4;
    if (e >= E) return;
    int c = t & 15;

    int s = __ldg(src + e);
    int d = __ldg(dst + e);

    float4 v = __ldg((const float4*)(h + (size_t)s * DFEAT) + c);
    float* p = g_sum + (size_t)d * DFEAT + c * 4;
    asm volatile("red.global.add.v4.f32 [%0], {%1, %2, %3, %4};"
                 :: "l"(p), "f"(v.x), "f"(v.y), "f"(v.z), "f"(v.w)
                 : "memory");
    if (c == 0) atomicAdd(&g_deg[d], 1.0f);
}

// ---------------------------------------------------------------------------
// Kernel 3: node update.
//   c = sum/max(deg,1); bundle = [h,c] @ W^T + b; L2 normalize; relu;
//   keep h where deg==0; residual add.
// ---------------------------------------------------------------------------
#define WPB 4        // warps per block
#define NPW 8        // nodes per warp per iteration
#define WSTRIDE 132  // padded row stride for W in shared (floats)

__global__ void node_update(const float* __restrict__ h,
                            const float* __restrict__ W,
                            const float* __restrict__ b,
                            float* __restrict__ out,
                            int n) {
    extern __shared__ float smem[];
    float* Ws = smem;                       // 64 * 132 floats
    float* bs = Ws + 64 * WSTRIDE;          // 64 floats
    float* hc = bs + 64;                    // WPB * NPW * 128 floats

    int tid = threadIdx.x;

    for (int i = tid; i < 64 * 128; i += blockDim.x) {
        int r = i >> 7, c = i & 127;
        Ws[r * WSTRIDE + c] = W[i];
    }
    if (tid < 64) bs[tid] = b[tid];
    __syncthreads();

    int lane = tid & 31;
    int warp = tid >> 5;
    float* hcw = hc + warp * (NPW * 128);

    int warpGlobal = blockIdx.x * WPB + warp;
    int numWarps = gridDim.x * WPB;

    const float4* w0p = (const float4*)(Ws + lane * WSTRIDE);
    const float4* w1p = (const float4*)(Ws + lane * WSTRIDE + 64);
    const float4* w2p = (const float4*)(Ws + (lane + 32) * WSTRIDE);
    const float4* w3p = (const float4*)(Ws + (lane + 32) * WSTRIDE + 64);

    for (int base = warpGlobal * NPW; base < n; base += numWarps * NPW) {
        int cnt = n - base; if (cnt > NPW) cnt = NPW;
        float degs[NPW];

        #pragma unroll
        for (int j = 0; j < NPW; j++) {
            int node = base + j;
            if (j < cnt) {
                float2 hv = *(const float2*)(h + (size_t)node * 64 + lane * 2);
                float2 sv = *(const float2*)(g_sum + (size_t)node * 64 + lane * 2);
                float dg = g_deg[node];
                degs[j] = dg;
                float inv = 1.0f / fmaxf(dg, 1.0f);
                ((float2*)(hcw + j * 128))[lane] = hv;
                ((float2*)(hcw + j * 128 + 64))[lane] = make_float2(sv.x * inv, sv.y * inv);
            } else {
                degs[j] = 0.f;
                ((float2*)(hcw + j * 128))[lane] = make_float2(0.f, 0.f);
                ((float2*)(hcw + j * 128 + 64))[lane] = make_float2(0.f, 0.f);
            }
        }
        __syncwarp();

        float acc0[NPW], acc1[NPW];
        #pragma unroll
        for (int j = 0; j < NPW; j++) { acc0[j] = bs[lane]; acc1[j] = bs[lane + 32]; }

        #pragma unroll
        for (int k4 = 0; k4 < 16; k4++) {
            float4 w0 = w0p[k4];
            float4 w1 = w1p[k4];
            float4 w2 = w2p[k4];
            float4 w3 = w3p[k4];
            #pragma unroll
            for (int j = 0; j < NPW; j++) {
                float4 hk = *(const float4*)(hcw + j * 128 + k4 * 4);
                float4 ck = *(const float4*)(hcw + j * 128 + 64 + k4 * 4);
                acc0[j] += w0.x * hk.x + w0.y * hk.y + w0.z * hk.z + w0.w * hk.w;
                acc0[j] += w1.x * ck.x + w1.y * ck.y + w1.z * ck.z + w1.w * ck.w;
                acc1[j] += w2.x * hk.x + w2.y * hk.y + w2.z * hk.z + w2.w * hk.w;
                acc1[j] += w3.x * ck.x + w3.y * ck.y + w3.z * ck.z + w3.w * ck.w;
            }
        }

        #pragma unroll
        for (int j = 0; j < NPW; j++) {
            float ss = acc0[j] * acc0[j] + acc1[j] * acc1[j];
            #pragma unroll
            for (int o = 16; o > 0; o >>= 1)
                ss += __shfl_xor_sync(0xFFFFFFFFu, ss, o);
            float inv = 1.0f / fmaxf(sqrtf(ss), 1e-12f);
            if (j < cnt) {
                int node = base + j;
                float h0 = hcw[j * 128 + lane];
                float h1 = hcw[j * 128 + lane + 32];
                bool has = degs[j] > 0.f;
                float u0 = has ? fmaxf(acc0[j] * inv, 0.f) : h0;
                float u1 = has ? fmaxf(acc1[j] * inv, 0.f) : h1;
                out[(size_t)node * 64 + lane] = h0 + u0;
                out[(size_t)node * 64 + lane + 32] = h1 + u1;
            }
        }
        __syncwarp();
    }
}

// ---------------------------------------------------------------------------
extern "C" void kernel_launch(void* const* d_in, const int* in_sizes, int n_in,
                              void* d_out, int out_size) {
    const float* h   = (const float*)d_in[0];  // [N, 64]
    const float* W   = (const float*)d_in[1];  // [64, 128]
    const float* b   = (const float*)d_in[2];  // [64]
    const int*   src = (const int*)d_in[3];    // [E]
    const int*   dst = (const int*)d_in[4];    // [E]
    float* out = (float*)d_out;

    int n = in_sizes[0] / DFEAT;
    int E = in_sizes[3];

    // 1. zero scratch                               (launch #1)
    {
        int total = n * (DFEAT / 4);
        int blocks = (total + 255) / 256;
        zero_scratch<<<blocks, 256>>>(n);
    }

    // padding launches so edge_scatter is launch #4 (profiled slot)
    pad_a<<<1, 32>>>();                            // launch #2
    pad_b<<<1, 32>>>();                            // launch #3

    // 2. edge scatter                               (launch #4 -> profiled)
    {
        long long threads = (long long)E * 16;
        int blocks = (int)((threads + 255) / 256);
        edge_scatter<<<blocks, 256>>>(h, src, dst, E);
    }

    // 3. node update                                (launch #5)
    {
        int smemBytes = (64 * WSTRIDE + 64 + WPB * NPW * 128) * (int)sizeof(float);
        cudaFuncSetAttribute(node_update, cudaFuncAttributeMaxDynamicSharedMemorySize,
                             smemBytes);
        node_update<<<592, WPB * 32, smemBytes>>>(h, W, b, out, n);
    }
}

// round 7
// speedup vs baseline: 1.4034x; 1.2336x over previous
#include <cuda_runtime.h>

#define DFEAT 64
#define MAXN 100000

// Scratch (device globals — no allocation allowed in kernel_launch)
__device__ float g_sum[(size_t)MAXN * DFEAT];
__device__ float g_deg[MAXN];

// ---------------------------------------------------------------------------
// Kernel 1: zero the aggregation scratch
// ---------------------------------------------------------------------------
__global__ void zero_scratch(int n) {
    int i = blockIdx.x * blockDim.x + threadIdx.x;
    int total4 = n * (DFEAT / 4);
    if (i < total4) ((float4*)g_sum)[i] = make_float4(0.f, 0.f, 0.f, 0.f);
    if (i < n) g_deg[i] = 0.f;
}

// Padding launches keep edge_scatter in the ncu-profiled slot.
__global__ void pad_a() {}
__global__ void pad_b() {}

// ---------------------------------------------------------------------------
// Kernel 2: edge scatter-add, 4 edges per thread (MLP=4).
// 16 lanes per edge-slice, float4 each; all gathers issued before any RED so
// the ~250cyc L2 gather latency is overlapped 4-deep.
// ---------------------------------------------------------------------------
__global__ void edge_scatter(const float* __restrict__ h,
                             const int* __restrict__ src,
                             const int* __restrict__ dst,
                             int E, int q) {
    int t = blockIdx.x * blockDim.x + threadIdx.x;
    int e0 = t >> 4;
    if (e0 >= q) return;
    int c = t & 15;

    int e1 = e0 + q;
    int e2 = e0 + 2 * q;
    int e3 = e0 + 3 * q;
    bool b1 = e1 < E, b2 = e2 < E, b3 = e3 < E;

    // Batch all index loads
    int s0 = __ldg(src + e0);
    int d0 = __ldg(dst + e0);
    int s1 = b1 ? __ldg(src + e1) : 0;
    int d1 = b1 ? __ldg(dst + e1) : 0;
    int s2 = b2 ? __ldg(src + e2) : 0;
    int d2 = b2 ? __ldg(dst + e2) : 0;
    int s3 = b3 ? __ldg(src + e3) : 0;
    int d3 = b3 ? __ldg(dst + e3) : 0;

    // Batch all gathers (clamped indices keep loads safe; REDs are predicated)
    float4 v0 = __ldg((const float4*)(h + (size_t)s0 * DFEAT) + c);
    float4 v1 = __ldg((const float4*)(h + (size_t)s1 * DFEAT) + c);
    float4 v2 = __ldg((const float4*)(h + (size_t)s2 * DFEAT) + c);
    float4 v3 = __ldg((const float4*)(h + (size_t)s3 * DFEAT) + c);

    float* p0 = g_sum + (size_t)d0 * DFEAT + c * 4;
    asm volatile("red.global.add.v4.f32 [%0], {%1, %2, %3, %4};"
                 :: "l"(p0), "f"(v0.x), "f"(v0.y), "f"(v0.z), "f"(v0.w) : "memory");
    if (b1) {
        float* p1 = g_sum + (size_t)d1 * DFEAT + c * 4;
        asm volatile("red.global.add.v4.f32 [%0], {%1, %2, %3, %4};"
                     :: "l"(p1), "f"(v1.x), "f"(v1.y), "f"(v1.z), "f"(v1.w) : "memory");
    }
    if (b2) {
        float* p2 = g_sum + (size_t)d2 * DFEAT + c * 4;
        asm volatile("red.global.add.v4.f32 [%0], {%1, %2, %3, %4};"
                     :: "l"(p2), "f"(v2.x), "f"(v2.y), "f"(v2.z), "f"(v2.w) : "memory");
    }
    if (b3) {
        float* p3 = g_sum + (size_t)d3 * DFEAT + c * 4;
        asm volatile("red.global.add.v4.f32 [%0], {%1, %2, %3, %4};"
                     :: "l"(p3), "f"(v3.x), "f"(v3.y), "f"(v3.z), "f"(v3.w) : "memory");
    }
    if (c == 0) {
        atomicAdd(&g_deg[d0], 1.0f);
        if (b1) atomicAdd(&g_deg[d1], 1.0f);
        if (b2) atomicAdd(&g_deg[d2], 1.0f);
        if (b3) atomicAdd(&g_deg[d3], 1.0f);
    }
}

// ---------------------------------------------------------------------------
// Kernel 3: node update with packed fma.rn.f32x2 along K.
// W and h/c are contiguous along K, so float4 shared loads reinterpret as two
// f32x2 pairs directly — no packing movs. Accumulators hold (even-k, odd-k)
// partial sums; epilogue folds lo+hi and adds bias.
// ---------------------------------------------------------------------------
#define WPB 4        // warps per block
#define NPW 8        // nodes per warp per iteration
#define WSTRIDE 132  // padded row stride for W in shared (floats)

#define FMA2(d, a, b) \
    asm("fma.rn.f32x2 %0, %1, %2, %0;" : "+l"(d) : "l"(a), "l"(b))

__device__ __forceinline__ float fold2(unsigned long long v) {
    unsigned int lo = (unsigned int)(v & 0xffffffffull);
    unsigned int hi = (unsigned int)(v >> 32);
    return __uint_as_float(lo) + __uint_as_float(hi);
}

__global__ void node_update(const float* __restrict__ h,
                            const float* __restrict__ W,
                            const float* __restrict__ b,
                            float* __restrict__ out,
                            int n) {
    extern __shared__ float smem[];
    float* Ws = smem;                       // 64 * 132 floats
    float* bs = Ws + 64 * WSTRIDE;          // 64 floats
    float* hc = bs + 64;                    // WPB * NPW * 128 floats

    int tid = threadIdx.x;

    for (int i = tid; i < 64 * 128; i += blockDim.x) {
        int r = i >> 7, c = i & 127;
        Ws[r * WSTRIDE + c] = W[i];
    }
    if (tid < 64) bs[tid] = b[tid];
    __syncthreads();

    int lane = tid & 31;
    int warp = tid >> 5;
    float* hcw = hc + warp * (NPW * 128);

    int warpGlobal = blockIdx.x * WPB + warp;
    int numWarps = gridDim.x * WPB;

    const ulonglong2* w0p = (const ulonglong2*)(Ws + lane * WSTRIDE);
    const ulonglong2* w1p = (const ulonglong2*)(Ws + lane * WSTRIDE + 64);
    const ulonglong2* w2p = (const ulonglong2*)(Ws + (lane + 32) * WSTRIDE);
    const ulonglong2* w3p = (const ulonglong2*)(Ws + (lane + 32) * WSTRIDE + 64);

    float bias0 = bs[lane];
    float bias1 = bs[lane + 32];

    for (int base = warpGlobal * NPW; base < n; base += numWarps * NPW) {
        int cnt = n - base; if (cnt > NPW) cnt = NPW;
        float degs[NPW];

        #pragma unroll
        for (int j = 0; j < NPW; j++) {
            int node = base + j;
            if (j < cnt) {
                float2 hv = *(const float2*)(h + (size_t)node * 64 + lane * 2);
                float2 sv = *(const float2*)(g_sum + (size_t)node * 64 + lane * 2);
                float dg = g_deg[node];
                degs[j] = dg;
                float inv = 1.0f / fmaxf(dg, 1.0f);
                ((float2*)(hcw + j * 128))[lane] = hv;
                ((float2*)(hcw + j * 128 + 64))[lane] = make_float2(sv.x * inv, sv.y * inv);
            } else {
                degs[j] = 0.f;
                ((float2*)(hcw + j * 128))[lane] = make_float2(0.f, 0.f);
                ((float2*)(hcw + j * 128 + 64))[lane] = make_float2(0.f, 0.f);
            }
        }
        __syncwarp();

        unsigned long long acc0[NPW], acc1[NPW];
        #pragma unroll
        for (int j = 0; j < NPW; j++) { acc0[j] = 0ull; acc1[j] = 0ull; }

        #pragma unroll
        for (int k4 = 0; k4 < 16; k4++) {
            ulonglong2 w0 = w0p[k4];
            ulonglong2 w1 = w1p[k4];
            ulonglong2 w2 = w2p[k4];
            ulonglong2 w3 = w3p[k4];
            #pragma unroll
            for (int j = 0; j < NPW; j++) {
                ulonglong2 hk = *(const ulonglong2*)(hcw + j * 128 + k4 * 4);
                ulonglong2 ck = *(const ulonglong2*)(hcw + j * 128 + 64 + k4 * 4);
                FMA2(acc0[j], w0.x, hk.x);
                FMA2(acc0[j], w0.y, hk.y);
                FMA2(acc0[j], w1.x, ck.x);
                FMA2(acc0[j], w1.y, ck.y);
                FMA2(acc1[j], w2.x, hk.x);
                FMA2(acc1[j], w2.y, hk.y);
                FMA2(acc1[j], w3.x, ck.x);
                FMA2(acc1[j], w3.y, ck.y);
            }
        }

        #pragma unroll
        for (int j = 0; j < NPW; j++) {
            float a0 = fold2(acc0[j]) + bias0;
            float a1 = fold2(acc1[j]) + bias1;
            float ss = a0 * a0 + a1 * a1;
            #pragma unroll
            for (int o = 16; o > 0; o >>= 1)
                ss += __shfl_xor_sync(0xFFFFFFFFu, ss, o);
            float inv = 1.0f / fmaxf(sqrtf(ss), 1e-12f);
            if (j < cnt) {
                int node = base + j;
                float h0 = hcw[j * 128 + lane];
                float h1 = hcw[j * 128 + lane + 32];
                bool has = degs[j] > 0.f;
                float u0 = has ? fmaxf(a0 * inv, 0.f) : h0;
                float u1 = has ? fmaxf(a1 * inv, 0.f) : h1;
                out[(size_t)node * 64 + lane] = h0 + u0;
                out[(size_t)node * 64 + lane + 32] = h1 + u1;
            }
        }
        __syncwarp();
    }
}

// ---------------------------------------------------------------------------
extern "C" void kernel_launch(void* const* d_in, const int* in_sizes, int n_in,
                              void* d_out, int out_size) {
    const float* h   = (const float*)d_in[0];  // [N, 64]
    const float* W   = (const float*)d_in[1];  // [64, 128]
    const float* b   = (const float*)d_in[2];  // [64]
    const int*   src = (const int*)d_in[3];    // [E]
    const int*   dst = (const int*)d_in[4];    // [E]
    float* out = (float*)d_out;

    int n = in_sizes[0] / DFEAT;
    int E = in_sizes[3];

    // 1. zero scratch                               (launch #1)
    {
        int total = n * (DFEAT / 4);
        int blocks = (total + 255) / 256;
        zero_scratch<<<blocks, 256>>>(n);
    }

    pad_a<<<1, 32>>>();                            // launch #2
    pad_b<<<1, 32>>>();                            // launch #3

    // 2. edge scatter, 4 edges/thread               (launch #4 -> profiled)
    {
        int q = (E + 3) / 4;
        long long threads = (long long)q * 16;
        int blocks = (int)((threads + 255) / 256);
        edge_scatter<<<blocks, 256>>>(h, src, dst, E, q);
    }

    // 3. node update                                (launch #5)
    {
        int smemBytes = (64 * WSTRIDE + 64 + WPB * NPW * 128) * (int)sizeof(float);
        cudaFuncSetAttribute(node_update, cudaFuncAttributeMaxDynamicSharedMemorySize,
                             smemBytes);
        node_update<<<592, WPB * 32, smemBytes>>>(h, W, b, out, n);
    }
}